// round 2
// baseline (speedup 1.0000x reference)
#include <cuda_runtime.h>
#include <math.h>

#define NB   8
#define GH   224
#define GW   224
#define RAD  3
#define DIAM 7
#define NP   49
#define TIL  16
#define HAL  22   // TIL + 2*RAD

// scratch (no allocations allowed)
__device__ float g_f0[NB * 972];
__device__ float g_bufA[NB * 3 * GH * GW];
__device__ float g_bufB[NB * 3 * GH * GW];

__device__ __forceinline__ int reflect224(int v) {
    if (v < 0) v = -v;
    if (v > 223) v = 446 - v;
    return v;
}

// ---------------------------------------------------------------------------
// K1: f0[b,j] = x[b,:] . W[j,:] + bias[j]     (one warp per output)
// ---------------------------------------------------------------------------
__global__ void k_linear(const float* __restrict__ x, const float* __restrict__ W,
                         const float* __restrict__ bias) {
    int gw = blockIdx.x * (blockDim.x >> 5) + (threadIdx.x >> 5);
    int lane = threadIdx.x & 31;
    if (gw >= NB * 972) return;
    int b = gw / 972, j = gw % 972;
    const float* xr = x + b * 1000;
    const float* wr = W + j * 1000;
    float acc = 0.f;
    for (int k = lane; k < 1000; k += 32) acc += xr[k] * wr[k];
    #pragma unroll
    for (int o = 16; o; o >>= 1) acc += __shfl_xor_sync(0xffffffffu, acc, o);
    if (lane == 0) g_f0[gw] = acc + bias[j];
}

// ---------------------------------------------------------------------------
// K2: bicubic 18 -> 224 (torch a=-0.75, align_corners=False, border clip)
// ---------------------------------------------------------------------------
__device__ __forceinline__ float cubw(float d) {
    d = fabsf(d);
    if (d <= 1.f) return (1.25f * d - 2.25f) * d * d + 1.f;
    if (d < 2.f)  return ((-0.75f * d + 3.75f) * d - 6.f) * d + 3.f;
    return 0.f;
}

__global__ void k_bicubic(float* __restrict__ dst) {
    int idx = blockIdx.x * blockDim.x + threadIdx.x;
    if (idx >= NB * 3 * GH * GW) return;
    int xo = idx % GW;
    int yo = (idx / GW) % GH;
    int bc = idx / (GH * GW);
    float fx = (xo + 0.5f) * (18.f / 224.f) - 0.5f;
    float fy = (yo + 0.5f) * (18.f / 224.f) - 0.5f;
    int x0 = (int)floorf(fx), y0 = (int)floorf(fy);
    float tx = fx - x0, ty = fy - y0;
    float wx[4], wy[4];
    int ix[4], iy[4];
    #pragma unroll
    for (int k = 0; k < 4; k++) {
        wx[k] = cubw(tx - (k - 1));
        wy[k] = cubw(ty - (k - 1));
        ix[k] = min(max(x0 + k - 1, 0), 17);
        iy[k] = min(max(y0 + k - 1, 0), 17);
    }
    const float* src = g_f0 + bc * 18 * 18;
    float acc = 0.f;
    #pragma unroll
    for (int a = 0; a < 4; a++) {
        float rs = 0.f;
        #pragma unroll
        for (int c = 0; c < 4; c++) rs += wx[c] * src[iy[a] * 18 + ix[c]];
        acc += wy[a] * rs;
    }
    dst[idx] = acc;
}

// ---------------------------------------------------------------------------
// K3: one JBU stage, fully fused.
// Shared: q halo (8 float4-chunks x 22x22), src halo (3 x 22x22), weights.
// ---------------------------------------------------------------------------
__global__ __launch_bounds__(256, 2) void k_stage(
    const float* __restrict__ src, float* __restrict__ dst,
    const float* __restrict__ guid,
    const float* __restrict__ w1s, const float* __restrict__ b1s,
    const float* __restrict__ w2s, const float* __restrict__ b2s,
    const float* __restrict__ temps, const float* __restrict__ sigmas, int s)
{
    extern __shared__ float4 sm4[];
    float4* shQ = sm4;                           // 8*22*22 float4
    float*  shS = (float*)(shQ + 8 * HAL * HAL); // 3*22*22 float
    float*  shW = shS + 3 * HAL * HAL;           // 1184: w1 96 | b1 32 | w2 1024 | b2 32

    const int tid = threadIdx.x;
    const int b = blockIdx.z;
    const int ty0 = blockIdx.y * TIL, tx0 = blockIdx.x * TIL;

    for (int i = tid; i < 1184; i += 256) {
        float v;
        if (i < 96)        v = w1s[s * 96 + i];
        else if (i < 128)  v = b1s[s * 32 + (i - 96)];
        else if (i < 1152) v = w2s[s * 1024 + (i - 128)];
        else               v = b2s[s * 32 + (i - 1152)];
        shW[i] = v;
    }
    __syncthreads();
    const float* w1 = shW;
    const float* b1 = shW + 96;
    const float4* w2v = (const float4*)(shW + 128);
    const float* b2 = shW + 1152;

    // fill halo: q (range-proj of guidance) + source channels, reflect-padded
    for (int hp = tid; hp < HAL * HAL; hp += 256) {
        int yy = hp / HAL, xx = hp % HAL;
        int gy = reflect224(ty0 + yy - RAD);
        int gx = reflect224(tx0 + xx - RAD);
        const float* gp = guid + ((size_t)(b * 3) * GH + gy) * GW + gx;
        float g0 = gp[0], g1 = gp[GH * GW], g2 = gp[2 * GH * GW];

        float u[32];
        #pragma unroll
        for (int k = 0; k < 32; k++) {
            float a = b1[k] + w1[k * 3] * g0 + w1[k * 3 + 1] * g1 + w1[k * 3 + 2] * g2;
            u[k] = 0.5f * a * (1.f + erff(a * 0.70710678118654752f)); // exact gelu
        }
        #pragma unroll
        for (int j4 = 0; j4 < 8; j4++) {
            float q0 = b2[j4 * 4 + 0], q1 = b2[j4 * 4 + 1];
            float q2 = b2[j4 * 4 + 2], q3 = b2[j4 * 4 + 3];
            #pragma unroll
            for (int kc = 0; kc < 8; kc++) {
                float4 a0 = w2v[(j4 * 4 + 0) * 8 + kc];
                float4 a1 = w2v[(j4 * 4 + 1) * 8 + kc];
                float4 a2 = w2v[(j4 * 4 + 2) * 8 + kc];
                float4 a3 = w2v[(j4 * 4 + 3) * 8 + kc];
                float u0 = u[kc * 4], u1 = u[kc * 4 + 1], u2 = u[kc * 4 + 2], u3 = u[kc * 4 + 3];
                q0 += a0.x * u0 + a0.y * u1 + a0.z * u2 + a0.w * u3;
                q1 += a1.x * u0 + a1.y * u1 + a1.z * u2 + a1.w * u3;
                q2 += a2.x * u0 + a2.y * u1 + a2.z * u2 + a2.w * u3;
                q3 += a3.x * u0 + a3.y * u1 + a3.z * u2 + a3.w * u3;
            }
            shQ[(j4 * HAL + yy) * HAL + xx] = make_float4(q0, q1, q2, q3);
        }
        const float* sp = src + ((size_t)(b * 3) * GH + gy) * GW + gx;
        shS[0 * HAL * HAL + hp] = sp[0];
        shS[1 * HAL * HAL + hp] = sp[GH * GW];
        shS[2 * HAL * HAL + hp] = sp[2 * GH * GW];
    }
    __syncthreads();

    const int ty = tid >> 4, tx = tid & 15;

    float4 qc[8];
    #pragma unroll
    for (int ch = 0; ch < 8; ch++)
        qc[ch] = shQ[(ch * HAL + ty + RAD) * HAL + (tx + RAD)];

    float scores[NP];
    #pragma unroll
    for (int p = 0; p < NP; p++) {
        const int dy = p / 7, dx = p % 7;
        float sacc = 0.f;
        #pragma unroll
        for (int ch = 0; ch < 8; ch++) {
            float4 v = shQ[(ch * HAL + ty + dy) * HAL + (tx + dx)];
            sacc += qc[ch].x * v.x + qc[ch].y * v.y + qc[ch].z * v.z + qc[ch].w * v.w;
        }
        scores[p] = sacc;
    }

    float t = expf(temps[s]);
    t = fminf(fmaxf(t, 1e-4f), 1e4f);

    float m = scores[0];
    #pragma unroll
    for (int p = 1; p < NP; p++) m = fmaxf(m, scores[p]);

    float sig = sigmas[s];
    float inv2s = 1.f / (2.f * sig * sig);
    float e1[7];
    #pragma unroll
    for (int i = 0; i < 7; i++) {
        float d = (i - 3) * (1.f / 3.f);
        e1[i] = expf(-d * d * inv2s);
    }

    float sum = 0.f, o0 = 0.f, o1 = 0.f, o2 = 0.f;
    #pragma unroll
    for (int p = 0; p < NP; p++) {
        const int dy = p / 7, dx = p % 7;
        float w = __expf(t * (scores[p] - m)) * (e1[dy] * e1[dx]);
        sum += w;
        const int hi = (ty + dy) * HAL + (tx + dx);
        o0 += w * shS[hi];
        o1 += w * shS[HAL * HAL + hi];
        o2 += w * shS[2 * HAL * HAL + hi];
    }
    float inv = 1.f / fmaxf(sum, 1e-30f);

    const int oy = ty0 + ty, ox = tx0 + tx;
    float* dp = dst + ((size_t)(b * 3) * GH + oy) * GW + ox;
    dp[0] = o0 * inv;
    dp[GH * GW] = o1 * inv;
    dp[2 * GH * GW] = o2 * inv;
}

// ---------------------------------------------------------------------------
extern "C" void kernel_launch(void* const* d_in, const int* in_sizes, int n_in,
                              void* d_out, int out_size) {
    const float* x      = (const float*)d_in[0];
    const float* guid   = (const float*)d_in[1];
    const float* lw     = (const float*)d_in[2];
    const float* lb     = (const float*)d_in[3];
    const float* w1s    = (const float*)d_in[4];
    const float* b1s    = (const float*)d_in[5];
    const float* w2s    = (const float*)d_in[6];
    const float* b2s    = (const float*)d_in[7];
    const float* temps  = (const float*)d_in[8];
    const float* sigmas = (const float*)d_in[9];
    float* out = (float*)d_out;

    void *pa, *pb;
    cudaGetSymbolAddress(&pa, g_bufA);
    cudaGetSymbolAddress(&pb, g_bufB);
    float* A  = (float*)pa;
    float* Bb = (float*)pb;

    const int smem = 8 * HAL * HAL * 16 + 3 * HAL * HAL * 4 + 1184 * 4; // 72496 B
    cudaFuncSetAttribute(k_stage, cudaFuncAttributeMaxDynamicSharedMemorySize, smem);

    k_linear<<<972, 256>>>(x, lw, lb);
    k_bicubic<<<(NB * 3 * GH * GW + 255) / 256, 256>>>(A);

    dim3 grid(GW / TIL, GH / TIL, NB);
    k_stage<<<grid, 256, smem>>>(A,  Bb,  guid, w1s, b1s, w2s, b2s, temps, sigmas, 0);
    k_stage<<<grid, 256, smem>>>(Bb, A,   guid, w1s, b1s, w2s, b2s, temps, sigmas, 1);
    k_stage<<<grid, 256, smem>>>(A,  Bb,  guid, w1s, b1s, w2s, b2s, temps, sigmas, 2);
    k_stage<<<grid, 256, smem>>>(Bb, out, guid, w1s, b1s, w2s, b2s, temps, sigmas, 3);
}

// round 4
// speedup vs baseline: 1.9263x; 1.9263x over previous
#include <cuda_runtime.h>
#include <cuda_fp16.h>
#include <math.h>

#define NB   8
#define GH   224
#define GW   224
#define RAD  3
#define DIAM 7
#define NP   49
#define TIL  16
#define HAL  22
#define NPIX (NB * GH * GW)
#define QSTRIDE 80   // bytes per pixel in shQ (5*16B -> conflict-free LDS.128)

// scratch (no allocations allowed)
__device__ float g_f0[NB * 972];
__device__ float g_bufA[NB * 3 * GH * GW];
__device__ float g_bufB[NB * 3 * GH * GW];
// q maps: [stage][pixel][4 x uint4] = 16 half2 (32 dims) per pixel, 64B/pixel
__device__ uint4 g_q[(size_t)4 * NPIX * 4];

__device__ __forceinline__ int reflect224(int v) {
    if (v < 0) v = -v;
    if (v > 223) v = 446 - v;
    return v;
}

// ---------------------------------------------------------------------------
// K1: linear 1000 -> 972, one warp per output
// ---------------------------------------------------------------------------
__global__ void k_linear(const float* __restrict__ x, const float* __restrict__ W,
                         const float* __restrict__ bias) {
    int gw = blockIdx.x * (blockDim.x >> 5) + (threadIdx.x >> 5);
    int lane = threadIdx.x & 31;
    if (gw >= NB * 972) return;
    int b = gw / 972, j = gw % 972;
    const float* xr = x + b * 1000;
    const float* wr = W + j * 1000;
    float acc = 0.f;
    for (int k = lane; k < 1000; k += 32) acc += xr[k] * wr[k];
    #pragma unroll
    for (int o = 16; o; o >>= 1) acc += __shfl_xor_sync(0xffffffffu, acc, o);
    if (lane == 0) g_f0[gw] = acc + bias[j];
}

// ---------------------------------------------------------------------------
// K2: bicubic 18 -> 224 (torch a=-0.75, align_corners=False)
// ---------------------------------------------------------------------------
__device__ __forceinline__ float cubw(float d) {
    d = fabsf(d);
    if (d <= 1.f) return (1.25f * d - 2.25f) * d * d + 1.f;
    if (d < 2.f)  return ((-0.75f * d + 3.75f) * d - 6.f) * d + 3.f;
    return 0.f;
}

__global__ void k_bicubic(float* __restrict__ dst) {
    int idx = blockIdx.x * blockDim.x + threadIdx.x;
    if (idx >= NB * 3 * GH * GW) return;
    int xo = idx % GW;
    int yo = (idx / GW) % GH;
    int bc = idx / (GH * GW);
    float fx = (xo + 0.5f) * (18.f / 224.f) - 0.5f;
    float fy = (yo + 0.5f) * (18.f / 224.f) - 0.5f;
    int x0 = (int)floorf(fx), y0 = (int)floorf(fy);
    float tx = fx - x0, ty = fy - y0;
    float wx[4], wy[4];
    int ix[4], iy[4];
    #pragma unroll
    for (int k = 0; k < 4; k++) {
        wx[k] = cubw(tx - (k - 1));
        wy[k] = cubw(ty - (k - 1));
        ix[k] = min(max(x0 + k - 1, 0), 17);
        iy[k] = min(max(y0 + k - 1, 0), 17);
    }
    const float* src = g_f0 + bc * 18 * 18;
    float acc = 0.f;
    #pragma unroll
    for (int a = 0; a < 4; a++) {
        float rs = 0.f;
        #pragma unroll
        for (int c = 0; c < 4; c++) rs += wx[c] * src[iy[a] * 18 + ix[c]];
        acc += wy[a] * rs;
    }
    dst[idx] = acc;
}

// ---------------------------------------------------------------------------
// K_qproj: q[s, pix, :] = W2 gelu(W1 g + b1) + b2, stored fp16.
// grid = (NPIX/256, 4 stages); one thread per pixel.
// ---------------------------------------------------------------------------
__global__ __launch_bounds__(256) void k_qproj(
    const float* __restrict__ guid,
    const float* __restrict__ w1s, const float* __restrict__ b1s,
    const float* __restrict__ w2s, const float* __restrict__ b2s)
{
    __shared__ float sw1[96];
    __shared__ float sb1[32];
    __shared__ __half2 sw2p[32][16];   // [k][j2] = (w2[2j2,k], w2[2j2+1,k])
    __shared__ __half2 sb2p[16];

    const int s = blockIdx.y;
    const int tid = threadIdx.x;
    if (tid < 96) sw1[tid] = w1s[s * 96 + tid];
    if (tid < 32) sb1[tid] = b1s[s * 32 + tid];
    for (int i = tid; i < 512; i += 256) {
        int k = i >> 4, j2 = i & 15;
        sw2p[k][j2] = __floats2half2_rn(w2s[s * 1024 + (2 * j2) * 32 + k],
                                        w2s[s * 1024 + (2 * j2 + 1) * 32 + k]);
    }
    if (tid < 16) sb2p[tid] = __floats2half2_rn(b2s[s * 32 + 2 * tid], b2s[s * 32 + 2 * tid + 1]);
    __syncthreads();

    const int pix = blockIdx.x * 256 + tid;     // NPIX = 1568*256, exact
    const int b = pix / (GH * GW);
    const int yx = pix % (GH * GW);
    const float* gp = guid + (size_t)b * 3 * GH * GW + yx;
    const float g0 = gp[0], g1 = gp[GH * GW], g2 = gp[2 * GH * GW];

    float u[32];
    #pragma unroll
    for (int k = 0; k < 32; k++) {
        float a = sb1[k] + sw1[k * 3] * g0 + sw1[k * 3 + 1] * g1 + sw1[k * 3 + 2] * g2;
        u[k] = 0.5f * a * (1.f + erff(a * 0.70710678118654752f));
    }
    __half2 acc[16];
    #pragma unroll
    for (int j = 0; j < 16; j++) acc[j] = sb2p[j];
    #pragma unroll
    for (int k = 0; k < 32; k++) {
        __half2 uk = __float2half2_rn(u[k]);
        #pragma unroll
        for (int j = 0; j < 16; j++) acc[j] = __hfma2(sw2p[k][j], uk, acc[j]);
    }
    uint4* dst = g_q + ((size_t)s * NPIX + pix) * 4;
    const uint4* av = (const uint4*)acc;
    dst[0] = av[0]; dst[1] = av[1]; dst[2] = av[2]; dst[3] = av[3];
}

// ---------------------------------------------------------------------------
// K_stage: fused scores (fp16) + softmax*spatial + 49-tap adaptive conv.
// ---------------------------------------------------------------------------
__global__ __launch_bounds__(256, 2) void k_stage(
    const float* __restrict__ src, float* __restrict__ dst,
    const float* __restrict__ temps, const float* __restrict__ sigmas, int s)
{
    extern __shared__ char sm[];
    char*   shQ = sm;                                // 484 * 80 B
    float4* shS = (float4*)(sm + HAL * HAL * QSTRIDE); // 484 float4

    const int tid = threadIdx.x;
    const int b = blockIdx.z;
    const int ty0 = blockIdx.y * TIL, tx0 = blockIdx.x * TIL;

    const uint4* qbase = g_q + (size_t)s * NPIX * 4;

    for (int hp = tid; hp < HAL * HAL; hp += 256) {
        int yy = hp / HAL, xx = hp % HAL;
        int gy = reflect224(ty0 + yy - RAD);
        int gx = reflect224(tx0 + xx - RAD);
        size_t pix = (size_t)b * GH * GW + (size_t)gy * GW + gx;
        const uint4* qp = qbase + pix * 4;
        uint4* qd = (uint4*)(shQ + hp * QSTRIDE);
        qd[0] = qp[0]; qd[1] = qp[1]; qd[2] = qp[2]; qd[3] = qp[3];
        const float* sp = src + (size_t)b * 3 * GH * GW + (size_t)gy * GW + gx;
        shS[hp] = make_float4(sp[0], sp[GH * GW], sp[2 * GH * GW], 0.f);
    }
    __syncthreads();

    const int ty = tid >> 4, tx = tid & 15;

    __half2 c2[16];
    {
        const uint4* cp = (const uint4*)(shQ + ((ty + RAD) * HAL + tx + RAD) * QSTRIDE);
        uint4* cv = (uint4*)c2;
        cv[0] = cp[0]; cv[1] = cp[1]; cv[2] = cp[2]; cv[3] = cp[3];
    }

    float scores[NP];
    #pragma unroll
    for (int p = 0; p < NP; p++) {
        const int dy = p / 7, dx = p % 7;
        const uint4* np = (const uint4*)(shQ + ((ty + dy) * HAL + tx + dx) * QSTRIDE);
        __half2 a = __float2half2_rn(0.f);
        #pragma unroll
        for (int i = 0; i < 4; i++) {
            uint4 v = np[i];
            const __half2* h = (const __half2*)&v;
            a = __hfma2(c2[i * 4 + 0], h[0], a);
            a = __hfma2(c2[i * 4 + 1], h[1], a);
            a = __hfma2(c2[i * 4 + 2], h[2], a);
            a = __hfma2(c2[i * 4 + 3], h[3], a);
        }
        float2 f = __half22float2(a);
        scores[p] = f.x + f.y;
    }

    float t = expf(temps[s]);
    t = fminf(fmaxf(t, 1e-4f), 1e4f);

    float m = scores[0];
    #pragma unroll
    for (int p = 1; p < NP; p++) m = fmaxf(m, scores[p]);

    const float sig = sigmas[s];
    const float inv2s = 1.f / (2.f * sig * sig);
    float e1[7];
    #pragma unroll
    for (int i = 0; i < 7; i++) {
        float d = (i - 3) * (1.f / 3.f);
        e1[i] = expf(-d * d * inv2s);
    }

    float sum = 0.f, o0 = 0.f, o1 = 0.f, o2 = 0.f;
    #pragma unroll
    for (int p = 0; p < NP; p++) {
        const int dy = p / 7, dx = p % 7;
        float w = __expf(t * (scores[p] - m)) * (e1[dy] * e1[dx]);
        sum += w;
        float4 sv = shS[(ty + dy) * HAL + tx + dx];
        o0 += w * sv.x;
        o1 += w * sv.y;
        o2 += w * sv.z;
    }
    float inv = 1.f / fmaxf(sum, 1e-30f);

    const int oy = ty0 + ty, ox = tx0 + tx;
    float* dp = dst + ((size_t)b * 3 * GH + oy) * GW + ox;
    dp[0] = o0 * inv;
    dp[GH * GW] = o1 * inv;
    dp[2 * GH * GW] = o2 * inv;
}

// ---------------------------------------------------------------------------
extern "C" void kernel_launch(void* const* d_in, const int* in_sizes, int n_in,
                              void* d_out, int out_size) {
    const float* x      = (const float*)d_in[0];
    const float* guid   = (const float*)d_in[1];
    const float* lw     = (const float*)d_in[2];
    const float* lb     = (const float*)d_in[3];
    const float* w1s    = (const float*)d_in[4];
    const float* b1s    = (const float*)d_in[5];
    const float* w2s    = (const float*)d_in[6];
    const float* b2s    = (const float*)d_in[7];
    const float* temps  = (const float*)d_in[8];
    const float* sigmas = (const float*)d_in[9];
    float* out = (float*)d_out;

    void *pa, *pb;
    cudaGetSymbolAddress(&pa, g_bufA);
    cudaGetSymbolAddress(&pb, g_bufB);
    float* A  = (float*)pa;
    float* Bb = (float*)pb;

    const int smem = HAL * HAL * QSTRIDE + HAL * HAL * 16;  // 38720 + 7744 = 46464 B
    cudaFuncSetAttribute(k_stage, cudaFuncAttributeMaxDynamicSharedMemorySize, smem);

    k_linear<<<972, 256>>>(x, lw, lb);
    k_bicubic<<<(NB * 3 * GH * GW + 255) / 256, 256>>>(A);

    dim3 qgrid(NPIX / 256, 4);
    k_qproj<<<qgrid, 256>>>(guid, w1s, b1s, w2s, b2s);

    dim3 grid(GW / TIL, GH / TIL, NB);
    k_stage<<<grid, 256, smem>>>(A,  Bb,  temps, sigmas, 0);
    k_stage<<<grid, 256, smem>>>(Bb, A,   temps, sigmas, 1);
    k_stage<<<grid, 256, smem>>>(A,  Bb,  temps, sigmas, 2);
    k_stage<<<grid, 256, smem>>>(Bb, out, temps, sigmas, 3);
}

// round 5
// speedup vs baseline: 2.4855x; 1.2903x over previous
#include <cuda_runtime.h>
#include <cuda_fp16.h>
#include <math.h>

#define NB   8
#define GH   224
#define GW   224
#define RAD  3
#define DIAM 7
#define NP   49
#define TW   16          // tile width
#define TH   32          // tile height (2 px per thread, vertical)
#define HC   22          // halo cols = TW + 6
#define HR   38          // halo rows = TH + 6
#define NHALO (HR * HC)  // 836
#define NPIX (NB * GH * GW)
#define QSTRIDE 80       // bytes per pixel in shQ (20 words: odd*4 -> conflict-free LDS.128)

// scratch (no allocations allowed)
__device__ float g_f0[NB * 972];
__device__ float g_bufA[NB * 3 * GH * GW];
__device__ float g_bufB[NB * 3 * GH * GW];
// q maps: [stage][pixel][4 x uint4] = 16 half2 (32 dims) per pixel, 64B/pixel
__device__ uint4 g_q[(size_t)4 * NPIX * 4];

__device__ __forceinline__ int reflect224(int v) {
    if (v < 0) v = -v;
    if (v > 223) v = 446 - v;
    return v;
}

// ---------------------------------------------------------------------------
// K1: linear 1000 -> 972, one warp per output
// ---------------------------------------------------------------------------
__global__ void k_linear(const float* __restrict__ x, const float* __restrict__ W,
                         const float* __restrict__ bias) {
    int gw = blockIdx.x * (blockDim.x >> 5) + (threadIdx.x >> 5);
    int lane = threadIdx.x & 31;
    if (gw >= NB * 972) return;
    int b = gw / 972, j = gw % 972;
    const float* xr = x + b * 1000;
    const float* wr = W + j * 1000;
    float acc = 0.f;
    for (int k = lane; k < 1000; k += 32) acc += xr[k] * wr[k];
    #pragma unroll
    for (int o = 16; o; o >>= 1) acc += __shfl_xor_sync(0xffffffffu, acc, o);
    if (lane == 0) g_f0[gw] = acc + bias[j];
}

// ---------------------------------------------------------------------------
// K2: bicubic 18 -> 224 (torch a=-0.75, align_corners=False)
// ---------------------------------------------------------------------------
__device__ __forceinline__ float cubw(float d) {
    d = fabsf(d);
    if (d <= 1.f) return (1.25f * d - 2.25f) * d * d + 1.f;
    if (d < 2.f)  return ((-0.75f * d + 3.75f) * d - 6.f) * d + 3.f;
    return 0.f;
}

__global__ void k_bicubic(float* __restrict__ dst) {
    int idx = blockIdx.x * blockDim.x + threadIdx.x;
    if (idx >= NB * 3 * GH * GW) return;
    int xo = idx % GW;
    int yo = (idx / GW) % GH;
    int bc = idx / (GH * GW);
    float fx = (xo + 0.5f) * (18.f / 224.f) - 0.5f;
    float fy = (yo + 0.5f) * (18.f / 224.f) - 0.5f;
    int x0 = (int)floorf(fx), y0 = (int)floorf(fy);
    float tx = fx - x0, ty = fy - y0;
    float wx[4], wy[4];
    int ix[4], iy[4];
    #pragma unroll
    for (int k = 0; k < 4; k++) {
        wx[k] = cubw(tx - (k - 1));
        wy[k] = cubw(ty - (k - 1));
        ix[k] = min(max(x0 + k - 1, 0), 17);
        iy[k] = min(max(y0 + k - 1, 0), 17);
    }
    const float* src = g_f0 + bc * 18 * 18;
    float acc = 0.f;
    #pragma unroll
    for (int a = 0; a < 4; a++) {
        float rs = 0.f;
        #pragma unroll
        for (int c = 0; c < 4; c++) rs += wx[c] * src[iy[a] * 18 + ix[c]];
        acc += wy[a] * rs;
    }
    dst[idx] = acc;
}

// ---------------------------------------------------------------------------
// K_qproj: q[s, pix, :] = W2 gelu(W1 g + b1) + b2, stored fp16.
// gelu via tanh.approx.f32 (matches exact gelu to ~1e-6 in this operand range)
// ---------------------------------------------------------------------------
__global__ __launch_bounds__(256) void k_qproj(
    const float* __restrict__ guid,
    const float* __restrict__ w1s, const float* __restrict__ b1s,
    const float* __restrict__ w2s, const float* __restrict__ b2s)
{
    __shared__ float sw1[96];
    __shared__ float sb1[32];
    __shared__ __half2 sw2p[32][16];   // [k][j2] = (w2[2j2,k], w2[2j2+1,k])
    __shared__ __half2 sb2p[16];

    const int s = blockIdx.y;
    const int tid = threadIdx.x;
    if (tid < 96) sw1[tid] = w1s[s * 96 + tid];
    if (tid < 32) sb1[tid] = b1s[s * 32 + tid];
    for (int i = tid; i < 512; i += 256) {
        int k = i >> 4, j2 = i & 15;
        sw2p[k][j2] = __floats2half2_rn(w2s[s * 1024 + (2 * j2) * 32 + k],
                                        w2s[s * 1024 + (2 * j2 + 1) * 32 + k]);
    }
    if (tid < 16) sb2p[tid] = __floats2half2_rn(b2s[s * 32 + 2 * tid], b2s[s * 32 + 2 * tid + 1]);
    __syncthreads();

    const int pix = blockIdx.x * 256 + tid;     // NPIX = 1568*256, exact
    const int b = pix / (GH * GW);
    const int yx = pix % (GH * GW);
    const float* gp = guid + (size_t)b * 3 * GH * GW + yx;
    const float g0 = gp[0], g1 = gp[GH * GW], g2 = gp[2 * GH * GW];

    float u[32];
    #pragma unroll
    for (int k = 0; k < 32; k++) {
        float a = sb1[k] + sw1[k * 3] * g0 + sw1[k * 3 + 1] * g1 + sw1[k * 3 + 2] * g2;
        float c = a * (0.7978845608028654f + 0.035677408136300125f * a * a);
        float th;
        asm("tanh.approx.f32 %0, %1;" : "=f"(th) : "f"(c));
        u[k] = 0.5f * a * (1.f + th);
    }
    __half2 acc[16];
    #pragma unroll
    for (int j = 0; j < 16; j++) acc[j] = sb2p[j];
    #pragma unroll
    for (int k = 0; k < 32; k++) {
        __half2 uk = __float2half2_rn(u[k]);
        #pragma unroll
        for (int j = 0; j < 16; j++) acc[j] = __hfma2(sw2p[k][j], uk, acc[j]);
    }
    uint4* dst = g_q + ((size_t)s * NPIX + pix) * 4;
    const uint4* av = (const uint4*)acc;
    dst[0] = av[0]; dst[1] = av[1]; dst[2] = av[2]; dst[3] = av[3];
}

// ---------------------------------------------------------------------------
// K_stage: fused scores + exp*spatial + 49-tap conv; 2 vertical pixels/thread.
// Each neighbor q/src smem load is shared between the two pixels.
// ---------------------------------------------------------------------------
__global__ __launch_bounds__(256, 2) void k_stage(
    const float* __restrict__ src, float* __restrict__ dst,
    const float* __restrict__ temps, const float* __restrict__ sigmas, int s)
{
    extern __shared__ char sm[];
    char*   shQ = sm;                              // NHALO * 80 B
    float4* shS = (float4*)(sm + NHALO * QSTRIDE); // NHALO float4

    const int tid = threadIdx.x;
    const int b = blockIdx.z;
    const int ty0 = blockIdx.y * TH, tx0 = blockIdx.x * TW;

    const uint4* qbase = g_q + (size_t)s * NPIX * 4;

    for (int hp = tid; hp < NHALO; hp += 256) {
        int yy = hp / HC, xx = hp % HC;
        int gy = reflect224(ty0 + yy - RAD);
        int gx = reflect224(tx0 + xx - RAD);
        size_t pix = (size_t)b * GH * GW + (size_t)gy * GW + gx;
        const uint4* qp = qbase + pix * 4;
        uint4* qd = (uint4*)(shQ + hp * QSTRIDE);
        qd[0] = qp[0]; qd[1] = qp[1]; qd[2] = qp[2]; qd[3] = qp[3];
        const float* sp = src + (size_t)b * 3 * GH * GW + (size_t)gy * GW + gx;
        shS[hp] = make_float4(sp[0], sp[GH * GW], sp[2 * GH * GW], 0.f);
    }
    __syncthreads();

    const int ty = tid >> 4, tx = tid & 15;   // pixel A = (2ty, tx), B = (2ty+1, tx)

    __half2 cA[16], cB[16];
    {
        const uint4* pa = (const uint4*)(shQ + ((2 * ty + RAD) * HC + tx + RAD) * QSTRIDE);
        const uint4* pb = (const uint4*)(shQ + ((2 * ty + RAD + 1) * HC + tx + RAD) * QSTRIDE);
        uint4* va = (uint4*)cA;
        uint4* vb = (uint4*)cB;
        #pragma unroll
        for (int i = 0; i < 4; i++) { va[i] = pa[i]; vb[i] = pb[i]; }
    }

    float t = expf(temps[s]);
    t = fminf(fmaxf(t, 1e-4f), 1e4f);

    const float sig = sigmas[s];
    const float inv2s = 1.f / (2.f * sig * sig);
    float e1[7];
    #pragma unroll
    for (int i = 0; i < 7; i++) {
        float d = (i - 3) * (1.f / 3.f);
        e1[i] = expf(-d * d * inv2s);
    }

    float sumA = 0.f, a0 = 0.f, a1 = 0.f, a2 = 0.f;
    float sumB = 0.f, bb0 = 0.f, bb1 = 0.f, bb2 = 0.f;

    #pragma unroll
    for (int dyp = 0; dyp < 8; dyp++) {
        const int r = 2 * ty + dyp;
        #pragma unroll
        for (int dx = 0; dx < 7; dx++) {
            const int hi = r * HC + tx + dx;
            uint4 n[4];
            const uint4* np = (const uint4*)(shQ + hi * QSTRIDE);
            n[0] = np[0]; n[1] = np[1]; n[2] = np[2]; n[3] = np[3];
            const __half2* h = (const __half2*)n;
            float4 sv = shS[hi];

            if (dyp < 7) {   // compile-time resolved in unrolled loop
                __half2 acc = __float2half2_rn(0.f);
                #pragma unroll
                for (int i = 0; i < 16; i++) acc = __hfma2(cA[i], h[i], acc);
                float2 f = __half22float2(acc);
                float w = __expf(t * (f.x + f.y)) * (e1[dyp] * e1[dx]);
                sumA += w; a0 += w * sv.x; a1 += w * sv.y; a2 += w * sv.z;
            }
            if (dyp > 0) {
                __half2 acc = __float2half2_rn(0.f);
                #pragma unroll
                for (int i = 0; i < 16; i++) acc = __hfma2(cB[i], h[i], acc);
                float2 f = __half22float2(acc);
                float w = __expf(t * (f.x + f.y)) * (e1[dyp - 1] * e1[dx]);
                sumB += w; bb0 += w * sv.x; bb1 += w * sv.y; bb2 += w * sv.z;
            }
        }
    }

    const float invA = 1.f / fmaxf(sumA, 1e-30f);
    const float invB = 1.f / fmaxf(sumB, 1e-30f);

    const int oy = ty0 + 2 * ty, ox = tx0 + tx;
    float* dp = dst + ((size_t)b * 3 * GH + oy) * GW + ox;
    dp[0]              = a0 * invA;
    dp[GH * GW]        = a1 * invA;
    dp[2 * GH * GW]    = a2 * invA;
    dp[GW]             = bb0 * invB;
    dp[GH * GW + GW]   = bb1 * invB;
    dp[2 * GH * GW + GW] = bb2 * invB;
}

// ---------------------------------------------------------------------------
extern "C" void kernel_launch(void* const* d_in, const int* in_sizes, int n_in,
                              void* d_out, int out_size) {
    const float* x      = (const float*)d_in[0];
    const float* guid   = (const float*)d_in[1];
    const float* lw     = (const float*)d_in[2];
    const float* lb     = (const float*)d_in[3];
    const float* w1s    = (const float*)d_in[4];
    const float* b1s    = (const float*)d_in[5];
    const float* w2s    = (const float*)d_in[6];
    const float* b2s    = (const float*)d_in[7];
    const float* temps  = (const float*)d_in[8];
    const float* sigmas = (const float*)d_in[9];
    float* out = (float*)d_out;

    void *pa, *pb;
    cudaGetSymbolAddress(&pa, g_bufA);
    cudaGetSymbolAddress(&pb, g_bufB);
    float* A  = (float*)pa;
    float* Bb = (float*)pb;

    const int smem = NHALO * QSTRIDE + NHALO * 16;  // 66880 + 13376 = 80256 B
    cudaFuncSetAttribute(k_stage, cudaFuncAttributeMaxDynamicSharedMemorySize, smem);

    k_linear<<<972, 256>>>(x, lw, lb);
    k_bicubic<<<(NB * 3 * GH * GW + 255) / 256, 256>>>(A);

    dim3 qgrid(NPIX / 256, 4);
    k_qproj<<<qgrid, 256>>>(guid, w1s, b1s, w2s, b2s);

    dim3 grid(GW / TW, GH / TH, NB);
    k_stage<<<grid, 256, smem>>>(A,  Bb,  temps, sigmas, 0);
    k_stage<<<grid, 256, smem>>>(Bb, A,   temps, sigmas, 1);
    k_stage<<<grid, 256, smem>>>(A,  Bb,  temps, sigmas, 2);
    k_stage<<<grid, 256, smem>>>(Bb, out, temps, sigmas, 3);
}

// round 7
// speedup vs baseline: 3.0337x; 1.2206x over previous
#include <cuda_runtime.h>
#include <cuda_fp16.h>
#include <math.h>

#define NB   8
#define GH   224
#define GW   224
#define RAD  3
#define DIAM 7
#define NP   49
#define TW   16          // tile width
#define TH   32          // tile height (2 px per thread, vertical)
#define HC   22          // halo cols = TW + 6
#define HR   38          // halo rows = TH + 6
#define NHALO (HR * HC)  // 836
#define NPIX (NB * GH * GW)
#define QW   12          // words per pixel q-record: 8 int8-words + scale + pad (48B)
#define LOG2E 1.4426950408889634f

// scratch (no allocations allowed)
__device__ float g_f0[NB * 972];
__device__ float g_bufA[NB * 3 * GH * GW];
__device__ float g_bufB[NB * 3 * GH * GW];
// q maps: [stage][pixel][12 words]: 32 x int8 q + fp32 per-pixel scale
__device__ unsigned int g_q[(size_t)4 * NPIX * QW];

__device__ __forceinline__ int reflect224(int v) {
    if (v < 0) v = -v;
    if (v > 223) v = 446 - v;
    return v;
}

// ---------------------------------------------------------------------------
// K1: linear 1000 -> 972, one warp per output
// ---------------------------------------------------------------------------
__global__ void k_linear(const float* __restrict__ x, const float* __restrict__ W,
                         const float* __restrict__ bias) {
    int gw = blockIdx.x * (blockDim.x >> 5) + (threadIdx.x >> 5);
    int lane = threadIdx.x & 31;
    if (gw >= NB * 972) return;
    int b = gw / 972, j = gw % 972;
    const float* xr = x + b * 1000;
    const float* wr = W + j * 1000;
    float acc = 0.f;
    for (int k = lane; k < 1000; k += 32) acc += xr[k] * wr[k];
    #pragma unroll
    for (int o = 16; o; o >>= 1) acc += __shfl_xor_sync(0xffffffffu, acc, o);
    if (lane == 0) g_f0[gw] = acc + bias[j];
}

// ---------------------------------------------------------------------------
// K2: bicubic 18 -> 224 (torch a=-0.75, align_corners=False)
// ---------------------------------------------------------------------------
__device__ __forceinline__ float cubw(float d) {
    d = fabsf(d);
    if (d <= 1.f) return (1.25f * d - 2.25f) * d * d + 1.f;
    if (d < 2.f)  return ((-0.75f * d + 3.75f) * d - 6.f) * d + 3.f;
    return 0.f;
}

__global__ void k_bicubic(float* __restrict__ dst) {
    int idx = blockIdx.x * blockDim.x + threadIdx.x;
    if (idx >= NB * 3 * GH * GW) return;
    int xo = idx % GW;
    int yo = (idx / GW) % GH;
    int bc = idx / (GH * GW);
    float fx = (xo + 0.5f) * (18.f / 224.f) - 0.5f;
    float fy = (yo + 0.5f) * (18.f / 224.f) - 0.5f;
    int x0 = (int)floorf(fx), y0 = (int)floorf(fy);
    float tx = fx - x0, ty = fy - y0;
    float wx[4], wy[4];
    int ix[4], iy[4];
    #pragma unroll
    for (int k = 0; k < 4; k++) {
        wx[k] = cubw(tx - (k - 1));
        wy[k] = cubw(ty - (k - 1));
        ix[k] = min(max(x0 + k - 1, 0), 17);
        iy[k] = min(max(y0 + k - 1, 0), 17);
    }
    const float* src = g_f0 + bc * 18 * 18;
    float acc = 0.f;
    #pragma unroll
    for (int a = 0; a < 4; a++) {
        float rs = 0.f;
        #pragma unroll
        for (int c = 0; c < 4; c++) rs += wx[c] * src[iy[a] * 18 + ix[c]];
        acc += wy[a] * rs;
    }
    dst[idx] = acc;
}

// ---------------------------------------------------------------------------
// K_qproj: q = W2 gelu(W1 g + b1) + b2, quantized to int8 + per-pixel scale.
// ---------------------------------------------------------------------------
__global__ __launch_bounds__(256) void k_qproj(
    const float* __restrict__ guid,
    const float* __restrict__ w1s, const float* __restrict__ b1s,
    const float* __restrict__ w2s, const float* __restrict__ b2s)
{
    __shared__ float sw1[96];
    __shared__ float sb1[32];
    __shared__ __half2 sw2p[32][16];   // [k][j2] = (w2[2j2,k], w2[2j2+1,k])
    __shared__ __half2 sb2p[16];

    const int s = blockIdx.y;
    const int tid = threadIdx.x;
    if (tid < 96) sw1[tid] = w1s[s * 96 + tid];
    if (tid < 32) sb1[tid] = b1s[s * 32 + tid];
    for (int i = tid; i < 512; i += 256) {
        int k = i >> 4, j2 = i & 15;
        sw2p[k][j2] = __floats2half2_rn(w2s[s * 1024 + (2 * j2) * 32 + k],
                                        w2s[s * 1024 + (2 * j2 + 1) * 32 + k]);
    }
    if (tid < 16) sb2p[tid] = __floats2half2_rn(b2s[s * 32 + 2 * tid], b2s[s * 32 + 2 * tid + 1]);
    __syncthreads();

    const int pix = blockIdx.x * 256 + tid;     // NPIX = 1568*256, exact
    const int b = pix / (GH * GW);
    const int yx = pix % (GH * GW);
    const float* gp = guid + (size_t)b * 3 * GH * GW + yx;
    const float g0 = gp[0], g1 = gp[GH * GW], g2 = gp[2 * GH * GW];

    float u[32];
    #pragma unroll
    for (int k = 0; k < 32; k++) {
        float a = sb1[k] + sw1[k * 3] * g0 + sw1[k * 3 + 1] * g1 + sw1[k * 3 + 2] * g2;
        float c = a * (0.7978845608028654f + 0.035677408136300125f * a * a);
        float th;
        asm("tanh.approx.f32 %0, %1;" : "=f"(th) : "f"(c));
        u[k] = 0.5f * a * (1.f + th);
    }
    __half2 acc[16];
    #pragma unroll
    for (int j = 0; j < 16; j++) acc[j] = sb2p[j];
    #pragma unroll
    for (int k = 0; k < 32; k++) {
        __half2 uk = __float2half2_rn(u[k]);
        #pragma unroll
        for (int j = 0; j < 16; j++) acc[j] = __hfma2(sw2p[k][j], uk, acc[j]);
    }

    // per-pixel absmax -> int8 quantize
    __half2 m2 = __habs2(acc[0]);
    #pragma unroll
    for (int j = 1; j < 16; j++) m2 = __hmax2(m2, __habs2(acc[j]));
    float mx = fmaxf(__low2float(m2), __high2float(m2));
    mx = fmaxf(mx, 1e-8f);
    float rscale = 127.f / mx;

    unsigned int ow[8];
    #pragma unroll
    for (int w = 0; w < 8; w++) {
        float2 fa = __half22float2(acc[2 * w]);
        float2 fb = __half22float2(acc[2 * w + 1]);
        int i0 = __float2int_rn(fa.x * rscale);
        int i1 = __float2int_rn(fa.y * rscale);
        int i2 = __float2int_rn(fb.x * rscale);
        int i3 = __float2int_rn(fb.y * rscale);
        ow[w] = (i0 & 255) | ((i1 & 255) << 8) | ((i2 & 255) << 16) | (i3 << 24);
    }
    unsigned int* dst = g_q + ((size_t)s * NPIX + pix) * QW;
    *(uint4*)dst       = make_uint4(ow[0], ow[1], ow[2], ow[3]);
    *(uint4*)(dst + 4) = make_uint4(ow[4], ow[5], ow[6], ow[7]);
    dst[8] = __float_as_uint(mx * (1.f / 127.f));
}

// ---------------------------------------------------------------------------
// K_stage: int8 dp4a scores + ex2 weights + 49-tap conv; 2 vertical px/thread.
// ---------------------------------------------------------------------------
__global__ __launch_bounds__(256, 3) void k_stage(
    const float* __restrict__ src, float* __restrict__ dst,
    const float* __restrict__ temps, const float* __restrict__ sigmas, int s)
{
    extern __shared__ unsigned int smu[];
    unsigned int* shQ = smu;                   // NHALO * 12 words (48B records)
    float4* shS = (float4*)(smu + NHALO * QW); // NHALO float4

    const int tid = threadIdx.x;
    const int b = blockIdx.z;
    const int ty0 = blockIdx.y * TH, tx0 = blockIdx.x * TW;

    const unsigned int* qbase = g_q + (size_t)s * NPIX * QW;

    for (int hp = tid; hp < NHALO; hp += 256) {
        int yy = hp / HC, xx = hp % HC;
        int gy = reflect224(ty0 + yy - RAD);
        int gx = reflect224(tx0 + xx - RAD);
        size_t pix = (size_t)b * GH * GW + (size_t)gy * GW + gx;
        const unsigned int* qp = qbase + pix * QW;
        unsigned int* qd = shQ + hp * QW;
        *(uint4*)qd       = *(const uint4*)qp;
        *(uint4*)(qd + 4) = *(const uint4*)(qp + 4);
        qd[8] = qp[8];
        const float* sp = src + (size_t)b * 3 * GH * GW + (size_t)gy * GW + gx;
        shS[hp] = make_float4(sp[0], sp[GH * GW], sp[2 * GH * GW], 0.f);
    }
    __syncthreads();

    const int ty = tid >> 4, tx = tid & 15;   // pixel A = (2ty, tx), B = (2ty+1, tx)

    int cA[8], cB[8];
    float preA, preB;

    float t = expf(temps[s]);
    t = fminf(fmaxf(t, 1e-4f), 1e4f);
    const float tl2e = t * LOG2E;

    {
        const unsigned int* pa = shQ + ((2 * ty + RAD) * HC + tx + RAD) * QW;
        const unsigned int* pb = shQ + ((2 * ty + RAD + 1) * HC + tx + RAD) * QW;
        *(uint4*)cA       = *(const uint4*)pa;
        *(uint4*)(cA + 4) = *(const uint4*)(pa + 4);
        *(uint4*)cB       = *(const uint4*)pb;
        *(uint4*)(cB + 4) = *(const uint4*)(pb + 4);
        preA = tl2e * __uint_as_float(pa[8]);
        preB = tl2e * __uint_as_float(pb[8]);
    }

    const float sig = sigmas[s];
    const float inv2s = 1.f / (2.f * sig * sig);
    float le[7];   // log2 of spatial weight
    #pragma unroll
    for (int i = 0; i < 7; i++) {
        float d = (i - 3) * (1.f / 3.f);
        le[i] = -d * d * inv2s * LOG2E;
    }

    float sumA = 0.f, a0 = 0.f, a1 = 0.f, a2 = 0.f;
    float sumB = 0.f, bb0 = 0.f, bb1 = 0.f, bb2 = 0.f;

    #pragma unroll
    for (int dyp = 0; dyp < 8; dyp++) {
        const int r = 2 * ty + dyp;
        #pragma unroll
        for (int dx = 0; dx < 7; dx++) {
            const int hi = r * HC + tx + dx;
            const unsigned int* np = shQ + hi * QW;
            int n[8];
            *(uint4*)n       = *(const uint4*)np;
            *(uint4*)(n + 4) = *(const uint4*)(np + 4);
            const float sn = __uint_as_float(np[8]);
            const float4 sv = shS[hi];

            if (dyp < 7) {   // pixel A
                int d = 0;
                #pragma unroll
                for (int i = 0; i < 8; i++) d = __dp4a(cA[i], n[i], d);
                float arg = fmaf(preA * sn, (float)d, le[dyp] + le[dx]);
                float w;
                asm("ex2.approx.f32 %0, %1;" : "=f"(w) : "f"(arg));
                sumA += w; a0 += w * sv.x; a1 += w * sv.y; a2 += w * sv.z;
            }
            if (dyp > 0) {   // pixel B
                int d = 0;
                #pragma unroll
                for (int i = 0; i < 8; i++) d = __dp4a(cB[i], n[i], d);
                float arg = fmaf(preB * sn, (float)d, le[dyp - 1] + le[dx]);
                float w;
                asm("ex2.approx.f32 %0, %1;" : "=f"(w) : "f"(arg));
                sumB += w; bb0 += w * sv.x; bb1 += w * sv.y; bb2 += w * sv.z;
            }
        }
    }

    const float invA = 1.f / fmaxf(sumA, 1e-30f);
    const float invB = 1.f / fmaxf(sumB, 1e-30f);

    const int oy = ty0 + 2 * ty, ox = tx0 + tx;
    float* dp = dst + ((size_t)b * 3 * GH + oy) * GW + ox;
    dp[0]                = a0 * invA;
    dp[GH * GW]          = a1 * invA;
    dp[2 * GH * GW]      = a2 * invA;
    dp[GW]               = bb0 * invB;
    dp[GH * GW + GW]     = bb1 * invB;
    dp[2 * GH * GW + GW] = bb2 * invB;
}

// ---------------------------------------------------------------------------
extern "C" void kernel_launch(void* const* d_in, const int* in_sizes, int n_in,
                              void* d_out, int out_size) {
    const float* x      = (const float*)d_in[0];
    const float* guid   = (const float*)d_in[1];
    const float* lw     = (const float*)d_in[2];
    const float* lb     = (const float*)d_in[3];
    const float* w1s    = (const float*)d_in[4];
    const float* b1s    = (const float*)d_in[5];
    const float* w2s    = (const float*)d_in[6];
    const float* b2s    = (const float*)d_in[7];
    const float* temps  = (const float*)d_in[8];
    const float* sigmas = (const float*)d_in[9];
    float* out = (float*)d_out;

    void *pa, *pb;
    cudaGetSymbolAddress(&pa, g_bufA);
    cudaGetSymbolAddress(&pb, g_bufB);
    float* A  = (float*)pa;
    float* Bb = (float*)pb;

    const int smem = NHALO * QW * 4 + NHALO * 16;  // 40128 + 13376 = 53504 B
    cudaFuncSetAttribute(k_stage, cudaFuncAttributeMaxDynamicSharedMemorySize, smem);

    k_linear<<<972, 256>>>(x, lw, lb);
    k_bicubic<<<(NB * 3 * GH * GW + 255) / 256, 256>>>(A);

    dim3 qgrid(NPIX / 256, 4);
    k_qproj<<<qgrid, 256>>>(guid, w1s, b1s, w2s, b2s);

    dim3 grid(GW / TW, GH / TH, NB);
    k_stage<<<grid, 256, smem>>>(A,  Bb,  temps, sigmas, 0);
    k_stage<<<grid, 256, smem>>>(Bb, A,   temps, sigmas, 1);
    k_stage<<<grid, 256, smem>>>(A,  Bb,  temps, sigmas, 2);
    k_stage<<<grid, 256, smem>>>(Bb, out, temps, sigmas, 3);
}

// round 9
// speedup vs baseline: 3.3780x; 1.1135x over previous
#include <cuda_runtime.h>
#include <cuda_fp16.h>
#include <math.h>

#define NB   8
#define GH   224
#define GW   224
#define RAD  3
#define DIAM 7
#define NP   49
#define TW   16          // tile width
#define TH   32          // tile height (4 px per thread, vertical)
#define HC   22          // halo cols = TW + 6
#define HR   38          // halo rows = TH + 6
#define NHALO (HR * HC)  // 836
#define NPIX (NB * GH * GW)
#define QW   12          // words/record: 8 int8-q words + scale (global); smem adds src
#define LOG2E 1.4426950408889634f

// scratch (no allocations allowed)
__device__ float g_f0[NB * 972];
__device__ float g_tmp[24 * 18 * 224];          // horizontal-pass bicubic temp
__device__ float g_bufA[NB * 3 * GH * GW];
__device__ float g_bufB[NB * 3 * GH * GW];
__device__ unsigned int g_q[(size_t)4 * NPIX * QW];   // per stage,pixel: q int8 x32 + scale
__device__ int g_w2q[4 * 32 * 8];               // w2 int8 rows
__device__ float g_w2s[4 * 32];                 // w2 per-row scales
__device__ float4 g_lutw[224];                  // bicubic weights
__device__ int4   g_luti[224];                  // bicubic indices

__device__ __forceinline__ int reflect224(int v) {
    if (v < 0) v = -v;
    if (v > 223) v = 446 - v;
    return v;
}

__device__ __forceinline__ float cubw(float d) {
    d = fabsf(d);
    if (d <= 1.f) return (1.25f * d - 2.25f) * d * d + 1.f;
    if (d < 2.f)  return ((-0.75f * d + 3.75f) * d - 6.f) * d + 3.f;
    return 0.f;
}

__device__ __forceinline__ int pack4(float a, float b, float c, float d, float rs) {
    int i0 = __float2int_rn(a * rs);
    int i1 = __float2int_rn(b * rs);
    int i2 = __float2int_rn(c * rs);
    int i3 = __float2int_rn(d * rs);
    return (i0 & 255) | ((i1 & 255) << 8) | ((i2 & 255) << 16) | (i3 << 24);
}

// ---------------------------------------------------------------------------
// K_init: bicubic LUT (threads 0..223) + w2 int8 quantization (threads 256..383)
// ---------------------------------------------------------------------------
__global__ void k_init(const float* __restrict__ w2s_) {
    int tid = threadIdx.x;
    if (tid < 224) {
        float fx = (tid + 0.5f) * (18.f / 224.f) - 0.5f;
        int x0 = (int)floorf(fx);
        float tx = fx - x0;
        float4 w; int4 ix;
        w.x = cubw(tx + 1.f); w.y = cubw(tx); w.z = cubw(tx - 1.f); w.w = cubw(tx - 2.f);
        ix.x = min(max(x0 - 1, 0), 17); ix.y = min(max(x0, 0), 17);
        ix.z = min(max(x0 + 1, 0), 17); ix.w = min(max(x0 + 2, 0), 17);
        g_lutw[tid] = w; g_luti[tid] = ix;
    } else if (tid >= 256) {
        int r = tid - 256;                 // 0..127 = stage*32 + row
        const float* row = w2s_ + r * 32;  // w2s is [4][32][32] contiguous
        float mx = 1e-12f;
        #pragma unroll
        for (int k = 0; k < 32; k++) mx = fmaxf(mx, fabsf(row[k]));
        float rs = 127.f / mx;
        #pragma unroll
        for (int w = 0; w < 8; w++)
            g_w2q[r * 8 + w] = pack4(row[4 * w], row[4 * w + 1], row[4 * w + 2], row[4 * w + 3], rs);
        g_w2s[r] = mx * (1.f / 127.f);
    }
}

// ---------------------------------------------------------------------------
// K1: linear 1000 -> 972, one warp per output
// ---------------------------------------------------------------------------
__global__ void k_linear(const float* __restrict__ x, const float* __restrict__ W,
                         const float* __restrict__ bias) {
    int gw = blockIdx.x * (blockDim.x >> 5) + (threadIdx.x >> 5);
    int lane = threadIdx.x & 31;
    if (gw >= NB * 972) return;
    int b = gw / 972, j = gw % 972;
    const float* xr = x + b * 1000;
    const float* wr = W + j * 1000;
    float acc = 0.f;
    for (int k = lane; k < 1000; k += 32) acc += xr[k] * wr[k];
    #pragma unroll
    for (int o = 16; o; o >>= 1) acc += __shfl_xor_sync(0xffffffffu, acc, o);
    if (lane == 0) g_f0[gw] = acc + bias[j];
}

// ---------------------------------------------------------------------------
// K2a: bicubic horizontal pass: [24][18][18] -> [24][18][224]
// ---------------------------------------------------------------------------
__global__ void k_bic1() {
    int idx = blockIdx.x * blockDim.x + threadIdx.x;   // 24*18*224 = 96768
    if (idx >= 24 * 18 * 224) return;
    int xo = idx % 224;
    int r  = (idx / 224) % 18;
    int bc = idx / (224 * 18);
    float4 w = g_lutw[xo];
    int4 ix = g_luti[xo];
    const float* row = g_f0 + bc * 324 + r * 18;
    g_tmp[idx] = w.x * row[ix.x] + w.y * row[ix.y] + w.z * row[ix.z] + w.w * row[ix.w];
}

// ---------------------------------------------------------------------------
// K2b: bicubic vertical pass: [24][18][224] -> [24][224][224]
// ---------------------------------------------------------------------------
__global__ void k_bic2(float* __restrict__ dst) {
    int idx = blockIdx.x * blockDim.x + threadIdx.x;   // 24*224*224
    if (idx >= 24 * 224 * 224) return;
    int xo = idx % 224;
    int yo = (idx / 224) % 224;
    int bc = idx / (224 * 224);
    float4 w = g_lutw[yo];
    int4 iy = g_luti[yo];
    const float* t = g_tmp + bc * 18 * 224 + xo;
    dst[idx] = w.x * t[iy.x * 224] + w.y * t[iy.y * 224]
             + w.z * t[iy.z * 224] + w.w * t[iy.w * 224];
}

// ---------------------------------------------------------------------------
// K_qproj: q = W2 gelu(W1 g + b1) + b2 via int8 dp4a, output int8 + scale.
// ---------------------------------------------------------------------------
__global__ __launch_bounds__(256) void k_qproj(
    const float* __restrict__ guid,
    const float* __restrict__ w1s, const float* __restrict__ b1s,
    const float* __restrict__ b2s)
{
    __shared__ float sw1[96];
    __shared__ float sb1[32];
    __shared__ float sb2[32];
    __shared__ float ssc[32];
    __shared__ int sw2q[32][8];

    const int s = blockIdx.y;
    const int tid = threadIdx.x;
    if (tid < 96) sw1[tid] = w1s[s * 96 + tid];
    if (tid < 32) {
        sb1[tid] = b1s[s * 32 + tid];
        sb2[tid] = b2s[s * 32 + tid];
        ssc[tid] = g_w2s[s * 32 + tid];
    }
    sw2q[tid >> 3][tid & 7] = g_w2q[(s * 32 + (tid >> 3)) * 8 + (tid & 7)];
    __syncthreads();

    const int pix = blockIdx.x * 256 + tid;     // NPIX = 1568*256, exact
    const int b = pix / (GH * GW);
    const int yx = pix % (GH * GW);
    const float* gp = guid + (size_t)b * 3 * GH * GW + yx;
    const float g0 = gp[0], g1 = gp[GH * GW], g2 = gp[2 * GH * GW];

    float u[32];
    float umax = 1e-12f;
    #pragma unroll
    for (int k = 0; k < 32; k++) {
        float a = sb1[k] + sw1[k * 3] * g0 + sw1[k * 3 + 1] * g1 + sw1[k * 3 + 2] * g2;
        float c = a * (0.7978845608028654f + 0.035677408136300125f * a * a);
        float th;
        asm("tanh.approx.f32 %0, %1;" : "=f"(th) : "f"(c));
        u[k] = 0.5f * a * (1.f + th);
        umax = fmaxf(umax, fabsf(u[k]));
    }
    const float ru = 127.f / umax;
    const float us = umax * (1.f / 127.f);
    int uw[8];
    #pragma unroll
    for (int w = 0; w < 8; w++)
        uw[w] = pack4(u[4 * w], u[4 * w + 1], u[4 * w + 2], u[4 * w + 3], ru);

    float qf[32];
    float qmax = 1e-12f;
    #pragma unroll
    for (int j = 0; j < 32; j++) {
        int d = 0;
        #pragma unroll
        for (int i = 0; i < 8; i++) d = __dp4a(uw[i], sw2q[j][i], d);
        qf[j] = fmaf((float)d, us * ssc[j], sb2[j]);
        qmax = fmaxf(qmax, fabsf(qf[j]));
    }
    const float rq = 127.f / qmax;
    unsigned int ow[8];
    #pragma unroll
    for (int w = 0; w < 8; w++)
        ow[w] = (unsigned int)pack4(qf[4 * w], qf[4 * w + 1], qf[4 * w + 2], qf[4 * w + 3], rq);

    unsigned int* dst = g_q + ((size_t)s * NPIX + pix) * QW;
    *(uint4*)dst       = make_uint4(ow[0], ow[1], ow[2], ow[3]);
    *(uint4*)(dst + 4) = make_uint4(ow[4], ow[5], ow[6], ow[7]);
    dst[8] = __float_as_uint(qmax * (1.f / 127.f));
}

// ---------------------------------------------------------------------------
// K_stage: int8 dp4a scores + ex2 + 49-tap conv; 4 vertical px/thread.
// smem record (48B): [q0..q7 | src0 src1 src2 | scale] -> 3x LDS.128 per tap.
// ---------------------------------------------------------------------------
__global__ __launch_bounds__(128, 4) void k_stage(
    const float* __restrict__ src, float* __restrict__ dst,
    const float* __restrict__ temps, const float* __restrict__ sigmas, int s)
{
    extern __shared__ unsigned int shQ[];      // NHALO * 12 words

    const int tid = threadIdx.x;
    const int b = blockIdx.z;
    const int ty0 = blockIdx.y * TH, tx0 = blockIdx.x * TW;

    const unsigned int* qbase = g_q + (size_t)s * NPIX * QW;

    for (int hp = tid; hp < NHALO; hp += 128) {
        int yy = hp / HC, xx = hp % HC;
        int gy = reflect224(ty0 + yy - RAD);
        int gx = reflect224(tx0 + xx - RAD);
        size_t pix = (size_t)b * GH * GW + (size_t)gy * GW + gx;
        const unsigned int* qp = qbase + pix * QW;
        unsigned int* qd = shQ + hp * QW;
        *(uint4*)qd       = *(const uint4*)qp;
        *(uint4*)(qd + 4) = *(const uint4*)(qp + 4);
        const float* sp = src + (size_t)b * 3 * GH * GW + (size_t)gy * GW + gx;
        *(float4*)(qd + 8) = make_float4(sp[0], sp[GH * GW], sp[2 * GH * GW],
                                         __uint_as_float(qp[8]));
    }
    __syncthreads();

    const int ty = tid >> 4, tx = tid & 15;   // pixels (4ty + p, tx), p = 0..3

    float t = expf(temps[s]);
    t = fminf(fmaxf(t, 1e-4f), 1e4f);
    const float tl2e = t * LOG2E;

    int c[4][8];
    float pre[4];
    #pragma unroll
    for (int p = 0; p < 4; p++) {
        const unsigned int* cp = shQ + ((4 * ty + p + RAD) * HC + tx + RAD) * QW;
        *(uint4*)&c[p][0] = *(const uint4*)cp;
        *(uint4*)&c[p][4] = *(const uint4*)(cp + 4);
        pre[p] = tl2e * __uint_as_float(cp[11]);
    }

    const float sig = sigmas[s];
    const float inv2s = 1.f / (2.f * sig * sig);
    float le[7];   // log2 spatial weight
    #pragma unroll
    for (int i = 0; i < 7; i++) {
        float d = (i - 3) * (1.f / 3.f);
        le[i] = -d * d * inv2s * LOG2E;
    }

    float sum[4] = {0.f, 0.f, 0.f, 0.f};
    float o0[4] = {0.f, 0.f, 0.f, 0.f};
    float o1[4] = {0.f, 0.f, 0.f, 0.f};
    float o2[4] = {0.f, 0.f, 0.f, 0.f};

    #pragma unroll
    for (int dyp = 0; dyp < 10; dyp++) {
        const int r = 4 * ty + dyp;
        #pragma unroll
        for (int dx = 0; dx < 7; dx++) {
            const unsigned int* np = shQ + (r * HC + tx + dx) * QW;
            int n[8];
            *(uint4*)&n[0] = *(const uint4*)np;
            *(uint4*)&n[4] = *(const uint4*)(np + 4);
            const float4 ss = *(const float4*)(np + 8);   // src0,src1,src2,scale
            #pragma unroll
            for (int p = 0; p < 4; p++) {
                if (dyp >= p && dyp < p + 7) {
                    int d = 0;
                    #pragma unroll
                    for (int i = 0; i < 8; i++) d = __dp4a(c[p][i], n[i], d);
                    float arg = fmaf(pre[p] * ss.w, (float)d, le[dyp - p] + le[dx]);
                    float w;
                    asm("ex2.approx.f32 %0, %1;" : "=f"(w) : "f"(arg));
                    sum[p] += w;
                    o0[p] += w * ss.x;
                    o1[p] += w * ss.y;
                    o2[p] += w * ss.z;
                }
            }
        }
    }

    const int ox = tx0 + tx;
    #pragma unroll
    for (int p = 0; p < 4; p++) {
        const float inv = 1.f / fmaxf(sum[p], 1e-30f);
        const int oy = ty0 + 4 * ty + p;
        float* dp = dst + ((size_t)b * 3 * GH + oy) * GW + ox;
        dp[0]           = o0[p] * inv;
        dp[GH * GW]     = o1[p] * inv;
        dp[2 * GH * GW] = o2[p] * inv;
    }
}

// ---------------------------------------------------------------------------
extern "C" void kernel_launch(void* const* d_in, const int* in_sizes, int n_in,
                              void* d_out, int out_size) {
    const float* x      = (const float*)d_in[0];
    const float* guid   = (const float*)d_in[1];
    const float* lw     = (const float*)d_in[2];
    const float* lb     = (const float*)d_in[3];
    const float* w1s    = (const float*)d_in[4];
    const float* b1s    = (const float*)d_in[5];
    const float* w2s    = (const float*)d_in[6];
    const float* b2s    = (const float*)d_in[7];
    const float* temps  = (const float*)d_in[8];
    const float* sigmas = (const float*)d_in[9];
    float* out = (float*)d_out;

    void *pa, *pb;
    cudaGetSymbolAddress(&pa, g_bufA);
    cudaGetSymbolAddress(&pb, g_bufB);
    float* A  = (float*)pa;
    float* Bb = (float*)pb;

    const int smem = NHALO * QW * 4;   // 40128 B
    cudaFuncSetAttribute(k_stage, cudaFuncAttributeMaxDynamicSharedMemorySize, smem);

    k_init<<<1, 384>>>(w2s);
    k_linear<<<972, 256>>>(x, lw, lb);
    k_bic1<<<(24 * 18 * 224 + 255) / 256, 256>>>();
    k_bic2<<<(24 * 224 * 224 + 255) / 256, 256>>>(A);

    dim3 qgrid(NPIX / 256, 4);
    k_qproj<<<qgrid, 256>>>(guid, w1s, b1s, b2s);

    dim3 grid(GW / TW, GH / TH, NB);
    k_stage<<<grid, 128, smem>>>(A,  Bb,  temps, sigmas, 0);
    k_stage<<<grid, 128, smem>>>(Bb, A,   temps, sigmas, 1);
    k_stage<<<grid, 128, smem>>>(A,  Bb,  temps, sigmas, 2);
    k_stage<<<grid, 128, smem>>>(Bb, out, temps, sigmas, 3);
}

// round 10
// speedup vs baseline: 3.5681x; 1.0563x over previous
#include <cuda_runtime.h>
#include <cuda_fp16.h>
#include <math.h>

#define NB   8
#define GH   224
#define GW   224
#define RAD  3
#define DIAM 7
#define TW   16          // tile width
#define TH   32          // tile height (4 px per thread, vertical)
#define HC   22          // halo cols = TW + 6
#define HR   38          // halo rows = TH + 6
#define NHALO (HR * HC)  // 836
#define NPIX (NB * GH * GW)          // 401408
#define QW   12
#define LOG2E 1.4426950408889634f
#define NSTAGE_BLKS 784              // 14 x 7 x 8 tiles
#define NQ_BLKS     3136             // NPIX / 128
#define NBIC_BLKS   9408             // 24*224*224 / 128

// scratch (no allocations allowed)
__device__ float g_f0[NB * 972];
__device__ float g_tmp[24 * 18 * 224];
__device__ float g_bufA[NB * 3 * GH * GW];
__device__ float g_bufB[NB * 3 * GH * GW];
__device__ unsigned int g_q[(size_t)4 * NPIX * QW];
__device__ int g_w2q[4 * 32 * 8];
__device__ float g_w2s[4 * 32];
__device__ float g_us[4];            // per-stage static u-scale
__device__ float4 g_lutw[224];
__device__ int4   g_luti[224];

__device__ __forceinline__ int reflect224(int v) {
    if (v < 0) v = -v;
    if (v > 223) v = 446 - v;
    return v;
}

__device__ __forceinline__ float cubw(float d) {
    d = fabsf(d);
    if (d <= 1.f) return (1.25f * d - 2.25f) * d * d + 1.f;
    if (d < 2.f)  return ((-0.75f * d + 3.75f) * d - 6.f) * d + 3.f;
    return 0.f;
}

__device__ __forceinline__ int pack4(float a, float b, float c, float d, float rs) {
    int i0 = __float2int_rn(a * rs);
    int i1 = __float2int_rn(b * rs);
    int i2 = __float2int_rn(c * rs);
    int i3 = __float2int_rn(d * rs);
    return (i0 & 255) | ((i1 & 255) << 8) | ((i2 & 255) << 16) | (i3 << 24);
}

// ---------------------------------------------------------------------------
// K_init: bicubic LUT + w2 int8 quantization + per-stage u bounds
// ---------------------------------------------------------------------------
__global__ void k_init(const float* __restrict__ w1s_, const float* __restrict__ b1s_,
                       const float* __restrict__ w2s_) {
    int tid = threadIdx.x;
    if (tid < 224) {
        float fx = (tid + 0.5f) * (18.f / 224.f) - 0.5f;
        int x0 = (int)floorf(fx);
        float tx = fx - x0;
        float4 w; int4 ix;
        w.x = cubw(tx + 1.f); w.y = cubw(tx); w.z = cubw(tx - 1.f); w.w = cubw(tx - 2.f);
        ix.x = min(max(x0 - 1, 0), 17); ix.y = min(max(x0, 0), 17);
        ix.z = min(max(x0 + 1, 0), 17); ix.w = min(max(x0 + 2, 0), 17);
        g_lutw[tid] = w; g_luti[tid] = ix;
    } else if (tid >= 256 && tid < 384) {
        int r = tid - 256;                 // stage*32 + row
        const float* row = w2s_ + r * 32;
        float mx = 1e-12f;
        #pragma unroll
        for (int k = 0; k < 32; k++) mx = fmaxf(mx, fabsf(row[k]));
        float rs = 127.f / mx;
        #pragma unroll
        for (int w = 0; w < 8; w++)
            g_w2q[r * 8 + w] = pack4(row[4 * w], row[4 * w + 1], row[4 * w + 2], row[4 * w + 3], rs);
        g_w2s[r] = mx * (1.f / 127.f);
    } else if (tid >= 384 && tid < 388) {
        int s = tid - 384;
        float ub = 0.2f;                   // gelu negative lobe bound
        for (int k = 0; k < 32; k++) {
            float bnd = fabsf(b1s_[s * 32 + k]);
            for (int c = 0; c < 3; c++) bnd += fabsf(w1s_[s * 96 + k * 3 + c]);
            ub = fmaxf(ub, bnd);           // |gelu(a)| <= max(0.2, |a|bound), g in [0,1]
        }
        g_us[s] = ub;
    }
}

// ---------------------------------------------------------------------------
// K1: linear 1000 -> 972, one warp per output
// ---------------------------------------------------------------------------
__global__ void k_linear(const float* __restrict__ x, const float* __restrict__ W,
                         const float* __restrict__ bias) {
    int gw = blockIdx.x * (blockDim.x >> 5) + (threadIdx.x >> 5);
    int lane = threadIdx.x & 31;
    if (gw >= NB * 972) return;
    int b = gw / 972, j = gw % 972;
    const float* xr = x + b * 1000;
    const float* wr = W + j * 1000;
    float acc = 0.f;
    for (int k = lane; k < 1000; k += 32) acc += xr[k] * wr[k];
    #pragma unroll
    for (int o = 16; o; o >>= 1) acc += __shfl_xor_sync(0xffffffffu, acc, o);
    if (lane == 0) g_f0[gw] = acc + bias[j];
}

// ---------------------------------------------------------------------------
// K2a: bicubic horizontal pass: [24][18][18] -> [24][18][224]
// ---------------------------------------------------------------------------
__global__ void k_bic1() {
    int idx = blockIdx.x * blockDim.x + threadIdx.x;
    if (idx >= 24 * 18 * 224) return;
    int xo = idx % 224;
    int r  = (idx / 224) % 18;
    int bc = idx / (224 * 18);
    float4 w = g_lutw[xo];
    int4 ix = g_luti[xo];
    const float* row = g_f0 + bc * 324 + r * 18;
    g_tmp[idx] = w.x * row[ix.x] + w.y * row[ix.y] + w.z * row[ix.z] + w.w * row[ix.w];
}

// ---------------------------------------------------------------------------
// qproj block role: 128 px per block, int8 dp4a matvec, static u-scale.
// ---------------------------------------------------------------------------
__device__ __forceinline__ void qproj_block(
    int s, int qbid, int tid,
    const float* __restrict__ guid,
    const float* __restrict__ w1s, const float* __restrict__ b1s,
    const float* __restrict__ b2s)
{
    __shared__ float sw1[96];
    __shared__ float sb1[32];
    __shared__ float sb2[32];
    __shared__ float ssc[32];
    __shared__ int sw2q[32][8];

    if (tid < 96) sw1[tid] = w1s[s * 96 + tid];
    if (tid < 32) {
        sb1[tid] = b1s[s * 32 + tid];
        sb2[tid] = b2s[s * 32 + tid];
        ssc[tid] = g_w2s[s * 32 + tid];
    }
    {
        int r = tid >> 2, c2 = (tid & 3) * 2;
        sw2q[r][c2]     = g_w2q[(s * 32 + r) * 8 + c2];
        sw2q[r][c2 + 1] = g_w2q[(s * 32 + r) * 8 + c2 + 1];
    }
    __syncthreads();

    const float uscale = g_us[s];
    const float ru = 127.f / uscale;
    const float us_ = uscale * (1.f / 127.f);

    const int pix = qbid * 128 + tid;
    const int b = pix / (GH * GW);
    const int yx = pix % (GH * GW);
    const float* gp = guid + (size_t)b * 3 * GH * GW + yx;
    const float g0 = gp[0], g1 = gp[GH * GW], g2 = gp[2 * GH * GW];

    float u[32];
    #pragma unroll
    for (int k = 0; k < 32; k++) {
        float a = sb1[k] + sw1[k * 3] * g0 + sw1[k * 3 + 1] * g1 + sw1[k * 3 + 2] * g2;
        float c = a * (0.7978845608028654f + 0.035677408136300125f * a * a);
        float th;
        asm("tanh.approx.f32 %0, %1;" : "=f"(th) : "f"(c));
        u[k] = 0.5f * a * (1.f + th);
    }
    int uw[8];
    #pragma unroll
    for (int w = 0; w < 8; w++)
        uw[w] = pack4(u[4 * w], u[4 * w + 1], u[4 * w + 2], u[4 * w + 3], ru);

    float qf[32];
    float qmax = 1e-12f;
    #pragma unroll
    for (int j = 0; j < 32; j++) {
        int d = 0;
        #pragma unroll
        for (int i = 0; i < 8; i++) d = __dp4a(uw[i], sw2q[j][i], d);
        qf[j] = fmaf((float)d, us_ * ssc[j], sb2[j]);
        qmax = fmaxf(qmax, fabsf(qf[j]));
    }
    const float rq = 127.f / qmax;
    unsigned int ow[8];
    #pragma unroll
    for (int w = 0; w < 8; w++)
        ow[w] = (unsigned int)pack4(qf[4 * w], qf[4 * w + 1], qf[4 * w + 2], qf[4 * w + 3], rq);

    unsigned int* dst = g_q + ((size_t)s * NPIX + pix) * QW;
    *(uint4*)dst       = make_uint4(ow[0], ow[1], ow[2], ow[3]);
    *(uint4*)(dst + 4) = make_uint4(ow[4], ow[5], ow[6], ow[7]);
    dst[8] = __float_as_uint(qmax * (1.f / 127.f));
}

// ---------------------------------------------------------------------------
// K_pre: bicubic vertical pass (blocks 0..9407) + qproj stage 0 (rest)
// ---------------------------------------------------------------------------
__global__ __launch_bounds__(128) void k_pre(
    float* __restrict__ dst, const float* __restrict__ guid,
    const float* __restrict__ w1s, const float* __restrict__ b1s,
    const float* __restrict__ b2s)
{
    const int bid = blockIdx.x;
    const int tid = threadIdx.x;
    if (bid >= NBIC_BLKS) {
        qproj_block(0, bid - NBIC_BLKS, tid, guid, w1s, b1s, b2s);
        return;
    }
    int idx = bid * 128 + tid;                  // 24*224*224 exact
    int xo = idx % 224;
    int yo = (idx / 224) % 224;
    int bc = idx / (224 * 224);
    float4 w = g_lutw[yo];
    int4 iy = g_luti[yo];
    const float* t = g_tmp + bc * 18 * 224 + xo;
    dst[idx] = w.x * t[iy.x * 224] + w.y * t[iy.y * 224]
             + w.z * t[iy.z * 224] + w.w * t[iy.w * 224];
}

// ---------------------------------------------------------------------------
// K_stage: stage-s JBU blocks (0..783) + qproj stage s+1 blocks (rest).
// ---------------------------------------------------------------------------
__global__ __launch_bounds__(128, 4) void k_stage(
    const float* __restrict__ src, float* __restrict__ dst,
    const float* __restrict__ guid,
    const float* __restrict__ w1s, const float* __restrict__ b1s,
    const float* __restrict__ b2s,
    const float* __restrict__ temps, const float* __restrict__ sigmas, int s)
{
    extern __shared__ unsigned int shQ[];      // NHALO * 12 words (stage role only)
    const int tid = threadIdx.x;
    const int bid = blockIdx.x;

    if (bid >= NSTAGE_BLKS) {
        qproj_block(s + 1, bid - NSTAGE_BLKS, tid, guid, w1s, b1s, b2s);
        return;
    }

    const int b = bid / 98;
    const int rem = bid % 98;
    const int ty0 = (rem / 14) * TH, tx0 = (rem % 14) * TW;

    const unsigned int* qbase = g_q + (size_t)s * NPIX * QW;

    for (int hp = tid; hp < NHALO; hp += 128) {
        int yy = hp / HC, xx = hp % HC;
        int gy = reflect224(ty0 + yy - RAD);
        int gx = reflect224(tx0 + xx - RAD);
        size_t pix = (size_t)b * GH * GW + (size_t)gy * GW + gx;
        const unsigned int* qp = qbase + pix * QW;
        unsigned int* qd = shQ + hp * QW;
        *(uint4*)qd       = *(const uint4*)qp;
        *(uint4*)(qd + 4) = *(const uint4*)(qp + 4);
        const float* sp = src + (size_t)b * 3 * GH * GW + (size_t)gy * GW + gx;
        *(float4*)(qd + 8) = make_float4(sp[0], sp[GH * GW], sp[2 * GH * GW],
                                         __uint_as_float(qp[8]));
    }
    __syncthreads();

    const int ty = tid >> 4, tx = tid & 15;   // pixels (4ty + p, tx), p = 0..3

    float t = expf(temps[s]);
    t = fminf(fmaxf(t, 1e-4f), 1e4f);
    const float tl2e = t * LOG2E;

    int c[4][8];
    float pre[4];
    #pragma unroll
    for (int p = 0; p < 4; p++) {
        const unsigned int* cp = shQ + ((4 * ty + p + RAD) * HC + tx + RAD) * QW;
        *(uint4*)&c[p][0] = *(const uint4*)cp;
        *(uint4*)&c[p][4] = *(const uint4*)(cp + 4);
        pre[p] = tl2e * __uint_as_float(cp[11]);
    }

    const float sig = sigmas[s];
    const float inv2s = 1.f / (2.f * sig * sig);
    float le[7];
    #pragma unroll
    for (int i = 0; i < 7; i++) {
        float d = (i - 3) * (1.f / 3.f);
        le[i] = -d * d * inv2s * LOG2E;
    }

    float sum[4] = {0.f, 0.f, 0.f, 0.f};
    float o0[4] = {0.f, 0.f, 0.f, 0.f};
    float o1[4] = {0.f, 0.f, 0.f, 0.f};
    float o2[4] = {0.f, 0.f, 0.f, 0.f};

    #pragma unroll
    for (int dyp = 0; dyp < 10; dyp++) {
        const int r = 4 * ty + dyp;
        #pragma unroll
        for (int dx = 0; dx < 7; dx++) {
            const unsigned int* np = shQ + (r * HC + tx + dx) * QW;
            int n[8];
            *(uint4*)&n[0] = *(const uint4*)np;
            *(uint4*)&n[4] = *(const uint4*)(np + 4);
            const float4 ss = *(const float4*)(np + 8);   // src0,src1,src2,scale
            #pragma unroll
            for (int p = 0; p < 4; p++) {
                if (dyp >= p && dyp < p + 7) {
                    int d = 0;
                    #pragma unroll
                    for (int i = 0; i < 8; i++) d = __dp4a(c[p][i], n[i], d);
                    float arg = fmaf(pre[p] * ss.w, (float)d, le[dyp - p] + le[dx]);
                    float w;
                    asm("ex2.approx.f32 %0, %1;" : "=f"(w) : "f"(arg));
                    sum[p] += w;
                    o0[p] += w * ss.x;
                    o1[p] += w * ss.y;
                    o2[p] += w * ss.z;
                }
            }
        }
    }

    const int ox = tx0 + tx;
    #pragma unroll
    for (int p = 0; p < 4; p++) {
        const float inv = 1.f / fmaxf(sum[p], 1e-30f);
        const int oy = ty0 + 4 * ty + p;
        float* dp = dst + ((size_t)b * 3 * GH + oy) * GW + ox;
        dp[0]           = o0[p] * inv;
        dp[GH * GW]     = o1[p] * inv;
        dp[2 * GH * GW] = o2[p] * inv;
    }
}

// ---------------------------------------------------------------------------
extern "C" void kernel_launch(void* const* d_in, const int* in_sizes, int n_in,
                              void* d_out, int out_size) {
    const float* x      = (const float*)d_in[0];
    const float* guid   = (const float*)d_in[1];
    const float* lw     = (const float*)d_in[2];
    const float* lb     = (const float*)d_in[3];
    const float* w1s    = (const float*)d_in[4];
    const float* b1s    = (const float*)d_in[5];
    const float* w2s    = (const float*)d_in[6];
    const float* b2s    = (const float*)d_in[7];
    const float* temps  = (const float*)d_in[8];
    const float* sigmas = (const float*)d_in[9];
    float* out = (float*)d_out;

    void *pa, *pb;
    cudaGetSymbolAddress(&pa, g_bufA);
    cudaGetSymbolAddress(&pb, g_bufB);
    float* A  = (float*)pa;
    float* Bb = (float*)pb;

    const int smem = NHALO * QW * 4;   // 40128 B
    cudaFuncSetAttribute(k_stage, cudaFuncAttributeMaxDynamicSharedMemorySize, smem);

    k_init<<<1, 512>>>(w1s, b1s, w2s);
    k_linear<<<972, 256>>>(x, lw, lb);
    k_bic1<<<(24 * 18 * 224 + 255) / 256, 256>>>();
    // bicubic vertical + qproj(stage 0) fused
    k_pre<<<NBIC_BLKS + NQ_BLKS, 128>>>(A, guid, w1s, b1s, b2s);
    // stage s + qproj(stage s+1) fused
    k_stage<<<NSTAGE_BLKS + NQ_BLKS, 128, smem>>>(A,  Bb,  guid, w1s, b1s, b2s, temps, sigmas, 0);
    k_stage<<<NSTAGE_BLKS + NQ_BLKS, 128, smem>>>(Bb, A,   guid, w1s, b1s, b2s, temps, sigmas, 1);
    k_stage<<<NSTAGE_BLKS + NQ_BLKS, 128, smem>>>(A,  Bb,  guid, w1s, b1s, b2s, temps, sigmas, 2);
    k_stage<<<NSTAGE_BLKS, 128, smem>>>(Bb, out, guid, w1s, b1s, b2s, temps, sigmas, 3);
}